// round 4
// baseline (speedup 1.0000x reference)
#include <cuda_runtime.h>
#include <cstdint>

#define NTIME 2000
#define NBATCH 128
#define INSIZE 256
#define OSIZE 40
#define NTRANS 32
#define NROWS (NTIME * NBATCH)

// Scratch: exp(trans), padded by 8 timesteps so the scan's register prefetch
// can read past the end without clamping (values never consumed).
__device__ float g_ew[(NTIME + 8) * NBATCH * NTRANS];
__device__ float g_logZ[NBATCH];   // already divided by NTIME

// ---------------- f32x2 packed helpers (Blackwell) ----------------
__device__ __forceinline__ unsigned long long pack2(float lo, float hi) {
    unsigned long long r;
    asm("mov.b64 %0, {%1, %2};" : "=l"(r) : "f"(lo), "f"(hi));
    return r;
}
__device__ __forceinline__ void unpack2(unsigned long long v, float& lo, float& hi) {
    asm("mov.b64 {%0, %1}, %2;" : "=f"(lo), "=f"(hi) : "l"(v));
}
__device__ __forceinline__ unsigned long long fma2(unsigned long long a,
                                                   unsigned long long b,
                                                   unsigned long long c) {
    unsigned long long d;
    asm("fma.rn.f32x2 %0, %1, %2, %3;" : "=l"(d) : "l"(a), "l"(b), "l"(c));
    return d;
}

__device__ __forceinline__ float softplus_f(float v) {
    // matches jax.nn.softplus = max(v,0) + log1p(exp(-|v|))
    return fmaxf(v, 0.0f) + log1pf(expf(-fabsf(v)));
}

// ---------------- Kernel 1: GEMM (f32x2) + activations + ew ----------------
// One thread per (t,b) row. W held in smem packed as output-pairs per k:
// wp[k*20+p] = packed(W[2p][k], W[2p+1][k]) so each fma.rn.f32x2 advances two
// output channels for one k.
__global__ void __launch_bounds__(256) k1_gemm_act(
    const float* __restrict__ x, const float* __restrict__ W,
    const float* __restrict__ bias, float* __restrict__ out)
{
    __shared__ __align__(16) unsigned long long wp[INSIZE * 20];  // 40 KB
    __shared__ float bs[OSIZE];

    int tid = threadIdx.x;
    for (int idx = tid; idx < INSIZE * 20; idx += 256) {
        int k = idx / 20, p = idx % 20;
        wp[idx] = pack2(W[(2 * p) * INSIZE + k], W[(2 * p + 1) * INSIZE + k]);
    }
    if (tid < OSIZE) bs[tid] = bias[tid];
    __syncthreads();

    int row = blockIdx.x * 256 + tid;             // grid sized exactly: no guard
    const float4* x4 = (const float4*)(x + (size_t)row * INSIZE);

    unsigned long long acc[20];
#pragma unroll
    for (int p = 0; p < 20; p++) acc[p] = pack2(bs[2 * p], bs[2 * p + 1]);

#pragma unroll 4
    for (int k0 = 0; k0 < INSIZE / 4; k0++) {
        float4 xv = x4[k0];
        float xs_[4] = {xv.x, xv.y, xv.z, xv.w};
#pragma unroll
        for (int kk = 0; kk < 4; kk++) {
            unsigned long long xx = pack2(xs_[kk], xs_[kk]);
            int k = k0 * 4 + kk;
            const ulonglong2* wr = (const ulonglong2*)(wp + k * 20);
#pragma unroll
            for (int j = 0; j < 10; j++) {
                ulonglong2 wv = wr[j];            // LDS.128: two output-pairs
                acc[2 * j]     = fma2(xx, wv.x, acc[2 * j]);
                acc[2 * j + 1] = fma2(xx, wv.y, acc[2 * j + 1]);
            }
        }
    }

    float y[OSIZE];
#pragma unroll
    for (int p = 0; p < 20; p++) unpack2(acc[p], y[2 * p], y[2 * p + 1]);

    float o[OSIZE];
#pragma unroll
    for (int c = 0; c < 4; c++) o[c] = 1.0f + softplus_f(y[c]);
#pragma unroll
    for (int c = 4; c < 8; c++) o[c] = 0.1f + softplus_f(y[c]);
    float ew[NTRANS];
#pragma unroll
    for (int c = 8; c < OSIZE; c++) {
        float tr = 5.0f * tanhf(y[c]);
        o[c] = tr;                      // logZ subtracted later by k3
        ew[c - 8] = __expf(tr);
    }

    float4* orow = (float4*)(out + (size_t)row * OSIZE);
#pragma unroll
    for (int q = 0; q < 10; q++)
        orow[q] = make_float4(o[4 * q], o[4 * q + 1], o[4 * q + 2], o[4 * q + 3]);

    float4* erow = (float4*)(g_ew + (size_t)row * NTRANS);
#pragma unroll
    for (int q = 0; q < 8; q++)
        erow[q] = make_float4(ew[4 * q], ew[4 * q + 1], ew[4 * q + 2], ew[4 * q + 3]);
}

// ---------------- Kernel 2: exp-domain CRF forward scan ----------------
__device__ __forceinline__ void loadE(float e[NTRANS], const float* p) {
    const float4* p4 = (const float4*)p;
#pragma unroll
    for (int q = 0; q < 8; q++) {
        float4 v = p4[q];
        e[4 * q] = v.x; e[4 * q + 1] = v.y; e[4 * q + 2] = v.z; e[4 * q + 3] = v.w;
    }
}

__device__ __forceinline__ void stepf(float p[8], const float e[NTRANS]) {
    float np[8];
#pragma unroll
    for (int i = 0; i < 4; i++) {
        float m = 0.0f, s = 0.0f;
#pragma unroll
        for (int j = 0; j < 8; j++) {
            float v = p[j] * e[i * 8 + j];
            if (j == i || j == i + 4) s += v;   // "stay" terms (diag mask)
            else                      m += v;   // "move" terms (holes mask)
        }
        np[i] = m;       // states 0..3 = move
        np[i + 4] = s;   // states 4..7 = stay
    }
#pragma unroll
    for (int i = 0; i < 8; i++) p[i] = np[i];
}

__global__ void __launch_bounds__(32, 1) k2_scan()
{
    int b = blockIdx.x * 32 + threadIdx.x;     // 4 blocks x 32 threads = 128 batches
    const float* bp = g_ew + (size_t)b * NTRANS;

    float p[8];
#pragma unroll
    for (int i = 0; i < 8; i++) p[i] = 1.0f;   // fwd0 = log 0 -> exp = 1
    float acc = 0.0f;

    float eA[NTRANS], eB[NTRANS], eC[NTRANS], eD[NTRANS];
    loadE(eA, bp + (size_t)0 * NBATCH * NTRANS);
    loadE(eB, bp + (size_t)1 * NBATCH * NTRANS);
    loadE(eC, bp + (size_t)2 * NBATCH * NTRANS);
    loadE(eD, bp + (size_t)3 * NBATCH * NTRANS);

    for (int t = 0; t < NTIME; t += 4) {
        stepf(p, eA); loadE(eA, bp + (size_t)(t + 4) * NBATCH * NTRANS);
        stepf(p, eB); loadE(eB, bp + (size_t)(t + 5) * NBATCH * NTRANS);
        stepf(p, eC); loadE(eC, bp + (size_t)(t + 6) * NBATCH * NTRANS);
        stepf(p, eD); loadE(eD, bp + (size_t)(t + 7) * NBATCH * NTRANS);
        if ((t & 7) == 4) {   // renormalize after every 8th step (after step t+3 ≡ 7 mod 8)
            float S = ((p[0] + p[1]) + (p[2] + p[3])) + ((p[4] + p[5]) + (p[6] + p[7]));
            float r = __fdividef(1.0f, S);
            acc += logf(S);
#pragma unroll
            for (int i = 0; i < 8; i++) p[i] *= r;
        }
    }

    float S = ((p[0] + p[1]) + (p[2] + p[3])) + ((p[4] + p[5]) + (p[6] + p[7]));
    g_logZ[b] = (acc + logf(S)) * (1.0f / (float)NTIME);
}

// ---------------- Kernel 3: out[..., 8:40] -= logZ[b] ----------------
__global__ void __launch_bounds__(256) k3_fixup(float* __restrict__ out)
{
    int q = blockIdx.x * 256 + threadIdx.x;          // one float4 of the 32 trans channels
    if (q >= NTIME * NBATCH * 8) return;
    int tb = q >> 3;
    int sub = q & 7;
    float lz = g_logZ[tb & (NBATCH - 1)];
    float4* ptr = (float4*)(out + (size_t)tb * OSIZE + 8) + sub;
    float4 v = *ptr;
    v.x -= lz; v.y -= lz; v.z -= lz; v.w -= lz;
    *ptr = v;
}

extern "C" void kernel_launch(void* const* d_in, const int* in_sizes, int n_in,
                              void* d_out, int out_size)
{
    const float* x = (const float*)d_in[0];
    const float* W = (const float*)d_in[1];
    const float* b = (const float*)d_in[2];
    float* out = (float*)d_out;

    k1_gemm_act<<<NROWS / 256, 256>>>(x, W, b, out);
    k2_scan<<<NBATCH / 32, 32>>>();
    k3_fixup<<<(NTIME * NBATCH * 8 + 255) / 256, 256>>>(out);
}

// round 6
// speedup vs baseline: 1.8125x; 1.8125x over previous
#include <cuda_runtime.h>
#include <cstdint>

#define NTIME 2000
#define NBATCH 128
#define INSIZE 256
#define OSIZE 40
#define NTRANS 32
#define NROWS (NTIME * NBATCH)
#define CHUNK 10
#define NCHUNK (NTIME / CHUNK)   // 200

// Scratch: exp(trans), padded by 8 timesteps so prefetch can read past the end.
__device__ float g_ew[(NTIME + 8) * NBATCH * NTRANS];
// Per-(chunk,batch) 8x8 transfer matrices (column-major per matrix), +1 chunk pad.
__device__ float g_chunkM[(NCHUNK + 1) * NBATCH * 64];
__device__ float g_logZ[NBATCH];   // already divided by NTIME

// ---------------- f32x2 packed helpers (Blackwell) ----------------
__device__ __forceinline__ unsigned long long pack2(float lo, float hi) {
    unsigned long long r;
    asm("mov.b64 %0, {%1, %2};" : "=l"(r) : "f"(lo), "f"(hi));
    return r;
}
__device__ __forceinline__ void unpack2(unsigned long long v, float& lo, float& hi) {
    asm("mov.b64 {%0, %1}, %2;" : "=f"(lo), "=f"(hi) : "l"(v));
}
__device__ __forceinline__ unsigned long long fma2(unsigned long long a,
                                                   unsigned long long b,
                                                   unsigned long long c) {
    unsigned long long d;
    asm("fma.rn.f32x2 %0, %1, %2, %3;" : "=l"(d) : "l"(a), "l"(b), "l"(c));
    return d;
}

__device__ __forceinline__ float softplus_f(float v) {
    // matches jax.nn.softplus = max(v,0) + log1p(exp(-|v|))
    return fmaxf(v, 0.0f) + log1pf(expf(-fabsf(v)));
}

// ---------------- Kernel 1: GEMM (f32x2, 2-row blocked) + activations + ew ----
// Each thread computes TWO rows (row, row+256): one weight LDS feeds two
// independent fma chains -> half the LDS traffic per output, double the ILP.
__global__ void __launch_bounds__(256) k1_gemm_act(
    const float* __restrict__ x, const float* __restrict__ W,
    const float* __restrict__ bias, float* __restrict__ out)
{
    __shared__ __align__(16) unsigned long long wp[INSIZE * 20];  // 40 KB
    __shared__ float bs[OSIZE];

    int tid = threadIdx.x;
    for (int idx = tid; idx < INSIZE * 20; idx += 256) {
        int k = idx / 20, p = idx % 20;
        wp[idx] = pack2(W[(2 * p) * INSIZE + k], W[(2 * p + 1) * INSIZE + k]);
    }
    if (tid < OSIZE) bs[tid] = bias[tid];
    __syncthreads();

    int row0 = blockIdx.x * 512 + tid;            // rows row0 and row0+256
    const float4* x4a = (const float4*)(x + (size_t)row0 * INSIZE);
    const float4* x4b = (const float4*)(x + (size_t)(row0 + 256) * INSIZE);

    unsigned long long acc[2][20];
#pragma unroll
    for (int p = 0; p < 20; p++) {
        unsigned long long bv = pack2(bs[2 * p], bs[2 * p + 1]);
        acc[0][p] = bv;
        acc[1][p] = bv;
    }

#pragma unroll 2
    for (int k0 = 0; k0 < INSIZE / 4; k0++) {
        float4 xva = x4a[k0];
        float4 xvb = x4b[k0];
        float xa_[4] = {xva.x, xva.y, xva.z, xva.w};
        float xb_[4] = {xvb.x, xvb.y, xvb.z, xvb.w};
#pragma unroll
        for (int kk = 0; kk < 4; kk++) {
            unsigned long long xxa = pack2(xa_[kk], xa_[kk]);
            unsigned long long xxb = pack2(xb_[kk], xb_[kk]);
            int k = k0 * 4 + kk;
            const ulonglong2* wr = (const ulonglong2*)(wp + k * 20);
#pragma unroll
            for (int j = 0; j < 10; j++) {
                ulonglong2 wv = wr[j];            // one LDS.128 -> 4 fma2
                acc[0][2 * j]     = fma2(xxa, wv.x, acc[0][2 * j]);
                acc[0][2 * j + 1] = fma2(xxa, wv.y, acc[0][2 * j + 1]);
                acc[1][2 * j]     = fma2(xxb, wv.x, acc[1][2 * j]);
                acc[1][2 * j + 1] = fma2(xxb, wv.y, acc[1][2 * j + 1]);
            }
        }
    }

#pragma unroll
    for (int r = 0; r < 2; r++) {
        int row = row0 + r * 256;
        float y[OSIZE];
#pragma unroll
        for (int p = 0; p < 20; p++) unpack2(acc[r][p], y[2 * p], y[2 * p + 1]);

        float o[OSIZE];
#pragma unroll
        for (int c = 0; c < 4; c++) o[c] = 1.0f + softplus_f(y[c]);
#pragma unroll
        for (int c = 4; c < 8; c++) o[c] = 0.1f + softplus_f(y[c]);
        float ew[NTRANS];
#pragma unroll
        for (int c = 8; c < OSIZE; c++) {
            float tr = 5.0f * tanhf(y[c]);
            o[c] = tr;                      // logZ subtracted later by k3
            ew[c - 8] = __expf(tr);
        }

        float4* orow = (float4*)(out + (size_t)row * OSIZE);
#pragma unroll
        for (int q = 0; q < 10; q++)
            orow[q] = make_float4(o[4 * q], o[4 * q + 1], o[4 * q + 2], o[4 * q + 3]);

        float4* erow = (float4*)(g_ew + (size_t)row * NTRANS);
#pragma unroll
        for (int q = 0; q < 8; q++)
            erow[q] = make_float4(ew[4 * q], ew[4 * q + 1], ew[4 * q + 2], ew[4 * q + 3]);
    }
}

// ---------------- CRF step in exp domain ----------------
__device__ __forceinline__ void loadE(float e[NTRANS], const float* p) {
    const float4* p4 = (const float4*)p;
#pragma unroll
    for (int q = 0; q < 8; q++) {
        float4 v = p4[q];
        e[4 * q] = v.x; e[4 * q + 1] = v.y; e[4 * q + 2] = v.z; e[4 * q + 3] = v.w;
    }
}

__device__ __forceinline__ void stepf(float p[8], const float e[NTRANS]) {
    float np[8];
#pragma unroll
    for (int i = 0; i < 4; i++) {
        float m = 0.0f, s = 0.0f;
#pragma unroll
        for (int j = 0; j < 8; j++) {
            float v = p[j] * e[i * 8 + j];
            if (j == i || j == i + 4) s += v;   // "stay" terms
            else                      m += v;   // "move" terms
        }
        np[i] = m;
        np[i + 4] = s;
    }
#pragma unroll
    for (int i = 0; i < 8; i++) p[i] = np[i];
}

// ---------------- Kernel 2a: per-chunk 8x8 transfer matrices ----------------
// One thread per (chunk, batch): propagate the 8 identity columns through
// CHUNK=10 steps. Entries bounded by (6e^5)^10 = e^68 < fp32 max -> no renorm.
__global__ void __launch_bounds__(128, 1) k2a_chunk()
{
    int b = threadIdx.x;           // batch
    int c = blockIdx.x;            // chunk
    const float* base = g_ew + ((size_t)c * CHUNK * NBATCH + b) * NTRANS;
    const size_t stride = (size_t)NBATCH * NTRANS;

    float M[8][8];                 // M[j] = column j (a p-vector)
#pragma unroll
    for (int j = 0; j < 8; j++)
#pragma unroll
        for (int i = 0; i < 8; i++) M[j][i] = (i == j) ? 1.0f : 0.0f;

    float eA[NTRANS], eB[NTRANS];
    loadE(eA, base);
#pragma unroll 1
    for (int s = 0; s < CHUNK; s += 2) {
        loadE(eB, base + (size_t)(s + 1) * stride);
#pragma unroll
        for (int j = 0; j < 8; j++) stepf(M[j], eA);
        loadE(eA, base + (size_t)(s + 2) * stride);   // s=8 reads pad: fine
#pragma unroll
        for (int j = 0; j < 8; j++) stepf(M[j], eB);
    }

    float4* dst = (float4*)(g_chunkM + ((size_t)c * NBATCH + b) * 64);
#pragma unroll
    for (int j = 0; j < 8; j++) {
        dst[2 * j]     = make_float4(M[j][0], M[j][1], M[j][2], M[j][3]);
        dst[2 * j + 1] = make_float4(M[j][4], M[j][5], M[j][6], M[j][7]);
    }
}

// ---------------- Kernel 2b: serial fold of chunk matrices per batch --------
__global__ void __launch_bounds__(128, 1) k2b_combine()
{
    int b = threadIdx.x;
    float v[8];
#pragma unroll
    for (int i = 0; i < 8; i++) v[i] = 1.0f;       // exp(fwd0) = ones
    float acc = 0.0f;

    float mA[64], mB[64];
    const float* src0 = g_chunkM + (size_t)b * 64;
    {
        const float4* p4 = (const float4*)src0;
#pragma unroll
        for (int q = 0; q < 16; q++) {
            float4 t = p4[q];
            mA[4 * q] = t.x; mA[4 * q + 1] = t.y; mA[4 * q + 2] = t.z; mA[4 * q + 3] = t.w;
        }
    }

#pragma unroll 1
    for (int c = 0; c < NCHUNK; c += 2) {
        // prefetch c+1 into mB (c+1 may hit the +1 pad chunk: harmless)
        {
            const float4* p4 = (const float4*)(g_chunkM + ((size_t)(c + 1) * NBATCH + b) * 64);
#pragma unroll
            for (int q = 0; q < 16; q++) {
                float4 t = p4[q];
                mB[4 * q] = t.x; mB[4 * q + 1] = t.y; mB[4 * q + 2] = t.z; mB[4 * q + 3] = t.w;
            }
        }
        // v <- mA * v ; renorm
        {
            float nv[8];
#pragma unroll
            for (int i = 0; i < 8; i++) nv[i] = 0.0f;
#pragma unroll
            for (int j = 0; j < 8; j++)
#pragma unroll
                for (int i = 0; i < 8; i++) nv[i] = fmaf(mA[j * 8 + i], v[j], nv[i]);
            float S = ((nv[0] + nv[1]) + (nv[2] + nv[3])) + ((nv[4] + nv[5]) + (nv[6] + nv[7]));
            acc += logf(S);
            float r = __fdividef(1.0f, S);
#pragma unroll
            for (int i = 0; i < 8; i++) v[i] = nv[i] * r;
        }
        // prefetch c+2 into mA (pad-guarded by loop bound: c+2 <= NCHUNK -> pad row ok)
        {
            const float4* p4 = (const float4*)(g_chunkM + ((size_t)(c + 2) * NBATCH + b) * 64);
#pragma unroll
            for (int q = 0; q < 16; q++) {
                float4 t = p4[q];
                mA[4 * q] = t.x; mA[4 * q + 1] = t.y; mA[4 * q + 2] = t.z; mA[4 * q + 3] = t.w;
            }
        }
        // v <- mB * v ; renorm
        {
            float nv[8];
#pragma unroll
            for (int i = 0; i < 8; i++) nv[i] = 0.0f;
#pragma unroll
            for (int j = 0; j < 8; j++)
#pragma unroll
                for (int i = 0; i < 8; i++) nv[i] = fmaf(mB[j * 8 + i], v[j], nv[i]);
            float S = ((nv[0] + nv[1]) + (nv[2] + nv[3])) + ((nv[4] + nv[5]) + (nv[6] + nv[7]));
            acc += logf(S);
            float r = __fdividef(1.0f, S);
#pragma unroll
            for (int i = 0; i < 8; i++) v[i] = nv[i] * r;
        }
    }

    g_logZ[b] = acc * (1.0f / (float)NTIME);
}

// ---------------- Kernel 3: out[..., 8:40] -= logZ[b] ----------------
__global__ void __launch_bounds__(256) k3_fixup(float* __restrict__ out)
{
    int q = blockIdx.x * 256 + threadIdx.x;      // one float4 of 32 trans channels
    if (q >= NTIME * NBATCH * 8) return;
    int tb = q >> 3;
    int sub = q & 7;
    float lz = g_logZ[tb & (NBATCH - 1)];
    float4* ptr = (float4*)(out + (size_t)tb * OSIZE + 8) + sub;
    float4 v = *ptr;
    v.x -= lz; v.y -= lz; v.z -= lz; v.w -= lz;
    *ptr = v;
}

extern "C" void kernel_launch(void* const* d_in, const int* in_sizes, int n_in,
                              void* d_out, int out_size)
{
    const float* x = (const float*)d_in[0];
    const float* W = (const float*)d_in[1];
    const float* b = (const float*)d_in[2];
    float* out = (float*)d_out;

    k1_gemm_act<<<NROWS / 512, 256>>>(x, W, b, out);
    k2a_chunk<<<NCHUNK, 128>>>();
    k2b_combine<<<1, 128>>>();
    k3_fixup<<<(NTIME * NBATCH * 8 + 255) / 256, 256>>>(out);
}

// round 7
// speedup vs baseline: 2.5960x; 1.4323x over previous
#include <cuda_runtime.h>
#include <cstdint>

#define NTIME 2000
#define NBATCH 128
#define INSIZE 256
#define OSIZE 40
#define NTRANS 32
#define NROWS (NTIME * NBATCH)
#define CHUNK 10
#define NCHUNK (NTIME / CHUNK)   // 200

// Scratch: exp(trans), padded by 8 timesteps so prefetch can read past the end.
__device__ float g_ew[(NTIME + 8) * NBATCH * NTRANS];
// Per-chunk 8x8 transfer matrices, coalesced layout:
// float4 index (c*16 + q)*128 + b, where q=2*j+h encodes column j, half h.
// +1 chunk of padding for the k2b prefetch.
__device__ float g_chunkM[(NCHUNK + 1) * NBATCH * 64];
__device__ float g_logZ[NBATCH];   // already divided by NTIME

// ---------------- f32x2 packed helpers (Blackwell) ----------------
__device__ __forceinline__ unsigned long long pack2(float lo, float hi) {
    unsigned long long r;
    asm("mov.b64 %0, {%1, %2};" : "=l"(r) : "f"(lo), "f"(hi));
    return r;
}
__device__ __forceinline__ void unpack2(unsigned long long v, float& lo, float& hi) {
    asm("mov.b64 {%0, %1}, %2;" : "=f"(lo), "=f"(hi) : "l"(v));
}
__device__ __forceinline__ unsigned long long fma2(unsigned long long a,
                                                   unsigned long long b,
                                                   unsigned long long c) {
    unsigned long long d;
    asm("fma.rn.f32x2 %0, %1, %2, %3;" : "=l"(d) : "l"(a), "l"(b), "l"(c));
    return d;
}
__device__ __forceinline__ unsigned long long add2(unsigned long long a,
                                                   unsigned long long b) {
    unsigned long long d;
    asm("add.rn.f32x2 %0, %1, %2;" : "=l"(d) : "l"(a), "l"(b));
    return d;
}
__device__ __forceinline__ unsigned long long mul2(unsigned long long a,
                                                   unsigned long long b) {
    unsigned long long d;
    asm("mul.rn.f32x2 %0, %1, %2;" : "=l"(d) : "l"(a), "l"(b));
    return d;
}

__device__ __forceinline__ float softplus_f(float v) {
    // matches jax.nn.softplus = max(v,0) + log1p(exp(-|v|))
    return fmaxf(v, 0.0f) + log1pf(expf(-fabsf(v)));
}

// ---------------- Kernel 1: GEMM (f32x2, 2-row x half-output) ---------------
// Thread (tid): half = tid>>7 selects output channels [half*20, half*20+20);
// lrow = tid&127 selects rows (blk*256+lrow) and (+128). Each warp is uniform
// in `half`, so the 5 weight LDS.128 per k stay single-address broadcasts.
// Accumulators: 2 rows x 10 pairs = 40 regs (no spill, ~3 blocks/SM).
__global__ void __launch_bounds__(256) k1_gemm_act(
    const float* __restrict__ x, const float* __restrict__ W,
    const float* __restrict__ bias, float* __restrict__ out)
{
    __shared__ __align__(16) unsigned long long wp[INSIZE * 20];  // 40 KB
    __shared__ float bs[OSIZE];

    int tid = threadIdx.x;
    for (int idx = tid; idx < INSIZE * 20; idx += 256) {
        int k = idx / 20, p = idx % 20;
        wp[idx] = pack2(W[(2 * p) * INSIZE + k], W[(2 * p + 1) * INSIZE + k]);
    }
    if (tid < OSIZE) bs[tid] = bias[tid];
    __syncthreads();

    int half = tid >> 7;            // 0: channels 0..19, 1: channels 20..39
    int lrow = tid & 127;
    int rowA = blockIdx.x * 256 + lrow;
    int rowB = rowA + 128;
    const float4* x4a = (const float4*)(x + (size_t)rowA * INSIZE);
    const float4* x4b = (const float4*)(x + (size_t)rowB * INSIZE);

    unsigned long long acc[2][10];
#pragma unroll
    for (int p = 0; p < 10; p++) {
        int g = half * 20 + 2 * p;
        unsigned long long bv = pack2(bs[g], bs[g + 1]);
        acc[0][p] = bv;
        acc[1][p] = bv;
    }

#pragma unroll 2
    for (int k0 = 0; k0 < INSIZE / 4; k0++) {
        float4 xva = x4a[k0];
        float4 xvb = x4b[k0];
        float xa_[4] = {xva.x, xva.y, xva.z, xva.w};
        float xb_[4] = {xvb.x, xvb.y, xvb.z, xvb.w};
#pragma unroll
        for (int kk = 0; kk < 4; kk++) {
            unsigned long long xxa = pack2(xa_[kk], xa_[kk]);
            unsigned long long xxb = pack2(xb_[kk], xb_[kk]);
            int k = k0 * 4 + kk;
            const ulonglong2* wr = (const ulonglong2*)(wp + k * 20 + half * 10);
#pragma unroll
            for (int j = 0; j < 5; j++) {
                ulonglong2 wv = wr[j];            // broadcast LDS.128 -> 4 fma2
                acc[0][2 * j]     = fma2(xxa, wv.x, acc[0][2 * j]);
                acc[0][2 * j + 1] = fma2(xxa, wv.y, acc[0][2 * j + 1]);
                acc[1][2 * j]     = fma2(xxb, wv.x, acc[1][2 * j]);
                acc[1][2 * j + 1] = fma2(xxb, wv.y, acc[1][2 * j + 1]);
            }
        }
    }

#pragma unroll
    for (int r = 0; r < 2; r++) {
        int row = (r == 0) ? rowA : rowB;
        float y[20];
#pragma unroll
        for (int p = 0; p < 10; p++) unpack2(acc[r][p], y[2 * p], y[2 * p + 1]);

        float o[20];
        float* orow = out + (size_t)row * OSIZE + half * 20;
        float* erow = g_ew + (size_t)row * NTRANS;

        if (half == 0) {
#pragma unroll
            for (int c = 0; c < 4; c++) o[c] = 1.0f + softplus_f(y[c]);
#pragma unroll
            for (int c = 4; c < 8; c++) o[c] = 0.1f + softplus_f(y[c]);
            float ew[12];
#pragma unroll
            for (int c = 8; c < 20; c++) {
                float tr = 5.0f * tanhf(y[c]);
                o[c] = tr;                        // logZ subtracted later by k3
                ew[c - 8] = __expf(tr);
            }
            float4* e4 = (float4*)erow;           // channels tr 0..11
#pragma unroll
            for (int q = 0; q < 3; q++)
                e4[q] = make_float4(ew[4 * q], ew[4 * q + 1], ew[4 * q + 2], ew[4 * q + 3]);
        } else {
            float ew[20];
#pragma unroll
            for (int c = 0; c < 20; c++) {
                float tr = 5.0f * tanhf(y[c]);
                o[c] = tr;
                ew[c] = __expf(tr);
            }
            float4* e4 = (float4*)(erow + 12);    // channels tr 12..31
#pragma unroll
            for (int q = 0; q < 5; q++)
                e4[q] = make_float4(ew[4 * q], ew[4 * q + 1], ew[4 * q + 2], ew[4 * q + 3]);
        }

        float4* o4 = (float4*)orow;
#pragma unroll
        for (int q = 0; q < 5; q++)
            o4[q] = make_float4(o[4 * q], o[4 * q + 1], o[4 * q + 2], o[4 * q + 3]);
    }
}

// ---------------- CRF step in exp domain ----------------
__device__ __forceinline__ void loadE(float e[NTRANS], const float* p) {
    const float4* p4 = (const float4*)p;
#pragma unroll
    for (int q = 0; q < 8; q++) {
        float4 v = p4[q];
        e[4 * q] = v.x; e[4 * q + 1] = v.y; e[4 * q + 2] = v.z; e[4 * q + 3] = v.w;
    }
}

__device__ __forceinline__ void stepf(float p[8], const float e[NTRANS]) {
    float np[8];
#pragma unroll
    for (int i = 0; i < 4; i++) {
        float m = 0.0f, s = 0.0f;
#pragma unroll
        for (int j = 0; j < 8; j++) {
            float v = p[j] * e[i * 8 + j];
            if (j == i || j == i + 4) s += v;   // "stay" terms
            else                      m += v;   // "move" terms
        }
        np[i] = m;
        np[i + 4] = s;
    }
#pragma unroll
    for (int i = 0; i < 8; i++) p[i] = np[i];
}

// ---------------- Kernel 2a: per-chunk 8x8 transfer matrices ----------------
// One thread per (chunk, batch): propagate the 8 identity columns through
// CHUNK=10 steps. Entries bounded by (6e^5)^10 = e^68 < fp32 max -> no renorm.
// Output stores are coalesced: float4 index (c*16 + q)*128 + b.
__global__ void __launch_bounds__(128, 1) k2a_chunk()
{
    int b = threadIdx.x;           // batch
    int c = blockIdx.x;            // chunk
    const float* base = g_ew + ((size_t)c * CHUNK * NBATCH + b) * NTRANS;
    const size_t stride = (size_t)NBATCH * NTRANS;

    float M[8][8];                 // M[j] = column j (a p-vector)
#pragma unroll
    for (int j = 0; j < 8; j++)
#pragma unroll
        for (int i = 0; i < 8; i++) M[j][i] = (i == j) ? 1.0f : 0.0f;

    float eA[NTRANS], eB[NTRANS];
    loadE(eA, base);
#pragma unroll 1
    for (int s = 0; s < CHUNK; s += 2) {
        loadE(eB, base + (size_t)(s + 1) * stride);
#pragma unroll
        for (int j = 0; j < 8; j++) stepf(M[j], eA);
        loadE(eA, base + (size_t)(s + 2) * stride);   // s=8 reads pad: fine
#pragma unroll
        for (int j = 0; j < 8; j++) stepf(M[j], eB);
    }

    float4* dst = (float4*)g_chunkM;
#pragma unroll
    for (int j = 0; j < 8; j++) {
        dst[((size_t)c * 16 + 2 * j)     * NBATCH + b] = make_float4(M[j][0], M[j][1], M[j][2], M[j][3]);
        dst[((size_t)c * 16 + 2 * j + 1) * NBATCH + b] = make_float4(M[j][4], M[j][5], M[j][6], M[j][7]);
    }
}

// ---------------- Kernel 2b: serial fold of chunk matrices (f32x2) ----------
// 4 blocks x 32 threads: one thread per batch, spread over 4 SMs.
// Matrix held as 32 u64 (column j = u64 indices 4j..4j+3, i-pairs).
__device__ __forceinline__ void loadM(unsigned long long m[32], int c, int b) {
    const float4* p4 = (const float4*)g_chunkM;
#pragma unroll
    for (int q = 0; q < 16; q++) {
        float4 t = p4[((size_t)c * 16 + q) * NBATCH + b];   // coalesced
        m[2 * q]     = pack2(t.x, t.y);
        m[2 * q + 1] = pack2(t.z, t.w);
    }
}

__device__ __forceinline__ void foldM(const unsigned long long m[32],
                                      float v[8], float& acc) {
    unsigned long long nv[4];
#pragma unroll
    for (int qq = 0; qq < 4; qq++) nv[qq] = pack2(0.0f, 0.0f);
#pragma unroll
    for (int j = 0; j < 8; j++) {
        unsigned long long vj = pack2(v[j], v[j]);
#pragma unroll
        for (int qq = 0; qq < 4; qq++)
            nv[qq] = fma2(m[4 * j + qq], vj, nv[qq]);
    }
    unsigned long long t = add2(add2(nv[0], nv[1]), add2(nv[2], nv[3]));
    float slo, shi;
    unpack2(t, slo, shi);
    float S = slo + shi;
    acc += logf(S);
    float r = __fdividef(1.0f, S);
    unsigned long long r2 = pack2(r, r);
#pragma unroll
    for (int qq = 0; qq < 4; qq++) {
        unsigned long long u = mul2(nv[qq], r2);
        unpack2(u, v[2 * qq], v[2 * qq + 1]);
    }
}

__global__ void __launch_bounds__(32, 1) k2b_combine()
{
    int b = blockIdx.x * 32 + threadIdx.x;
    float v[8];
#pragma unroll
    for (int i = 0; i < 8; i++) v[i] = 1.0f;       // exp(fwd0) = ones
    float acc = 0.0f;

    unsigned long long mA[32], mB[32];
    loadM(mA, 0, b);

#pragma unroll 1
    for (int c = 0; c < NCHUNK; c += 2) {
        loadM(mB, c + 1, b);       // c+1 <= 199 valid
        foldM(mA, v, acc);
        loadM(mA, c + 2, b);       // c+2 may hit pad chunk 200: harmless
        foldM(mB, v, acc);
    }

    g_logZ[b] = acc * (1.0f / (float)NTIME);
}

// ---------------- Kernel 3: out[..., 8:40] -= logZ[b] ----------------
__global__ void __launch_bounds__(256) k3_fixup(float* __restrict__ out)
{
    int q = blockIdx.x * 256 + threadIdx.x;      // one float4 of 32 trans channels
    if (q >= NTIME * NBATCH * 8) return;
    int tb = q >> 3;
    int sub = q & 7;
    float lz = g_logZ[tb & (NBATCH - 1)];
    float4* ptr = (float4*)(out + (size_t)tb * OSIZE + 8) + sub;
    float4 v = *ptr;
    v.x -= lz; v.y -= lz; v.z -= lz; v.w -= lz;
    *ptr = v;
}

extern "C" void kernel_launch(void* const* d_in, const int* in_sizes, int n_in,
                              void* d_out, int out_size)
{
    const float* x = (const float*)d_in[0];
    const float* W = (const float*)d_in[1];
    const float* b = (const float*)d_in[2];
    float* out = (float*)d_out;

    k1_gemm_act<<<NROWS / 256, 256>>>(x, W, b, out);
    k2a_chunk<<<NCHUNK, 128>>>();
    k2b_combine<<<NBATCH / 32, 32>>>();
    k3_fixup<<<(NTIME * NBATCH * 8 + 255) / 256, 256>>>(out);
}